// round 1
// baseline (speedup 1.0000x reference)
#include <cuda_runtime.h>
#include <math.h>

#define DIM 128
#define TR 64
#define XS 132            // padded smem row stride (floats)
#define NTHREADS 256
#define MAXN 50000

// scratch (allocation-free rule: device globals)
__device__ float g_X[(size_t)MAXN * DIM];
__device__ float g_AGG[(size_t)MAXN * DIM];
__device__ float g_OUT[(size_t)MAXN * DIM];

#define SMEM_MLP  ((TR * XS + DIM * DIM) * 4)
#define SMEM_GATE ((3 * TR * XS + DIM * DIM) * 4)

// ---------------------------------------------------------------------------
__global__ void zero_kernel(float4* __restrict__ p, int n4) {
    int i = blockIdx.x * blockDim.x + threadIdx.x;
    if (i < n4) p[i] = make_float4(0.f, 0.f, 0.f, 0.f);
}

// ---------------------------------------------------------------------------
// Fused 2-layer MLP: out = relu(in @ W1 + b1) @ W2 + b2
// Block: 64 rows. Thread (tr,tc) computes a 4x8 register tile.
__global__ void __launch_bounds__(NTHREADS, 2)
mlp2_kernel(const float* __restrict__ in,
            const float* __restrict__ W1, const float* __restrict__ b1,
            const float* __restrict__ W2, const float* __restrict__ b2,
            float* __restrict__ out, int nrows)
{
    extern __shared__ float smem[];
    float* xs = smem;              // [TR][XS] activations (row-major)
    float* ws = smem + TR * XS;    // [128][128] weights
    const int tid = threadIdx.x;
    const int tc = tid & 15;       // col group: cols 8*tc .. 8*tc+7
    const int tr = tid >> 4;       // row group: rows 4*tr .. 4*tr+3
    const int row0 = blockIdx.x * TR;
    const int cbase = 8 * tc;

    // load input tile (coalesced, float4)
    for (int i = tid; i < TR * (DIM / 4); i += NTHREADS) {
        int r = i >> 5;            // 32 float4 per row
        int c4 = i & 31;
        float4 v = make_float4(0.f, 0.f, 0.f, 0.f);
        if (row0 + r < nrows)
            v = reinterpret_cast<const float4*>(in + (size_t)(row0 + r) * DIM)[c4];
        reinterpret_cast<float4*>(xs + r * XS)[c4] = v;
    }
    // load W1
    for (int i = tid; i < DIM * DIM / 4; i += NTHREADS)
        reinterpret_cast<float4*>(ws)[i] = reinterpret_cast<const float4*>(W1)[i];
    __syncthreads();

    float acc[4][8];
    #pragma unroll
    for (int i = 0; i < 4; i++)
        #pragma unroll
        for (int j = 0; j < 8; j++) acc[i][j] = 0.f;

    #pragma unroll 4
    for (int k = 0; k < DIM; k++) {
        float av[4];
        #pragma unroll
        for (int i = 0; i < 4; i++) av[i] = xs[(4 * tr + i) * XS + k];
        float4 w0 = reinterpret_cast<const float4*>(ws + k * DIM)[2 * tc];
        float4 w1 = reinterpret_cast<const float4*>(ws + k * DIM)[2 * tc + 1];
        float wb[8] = {w0.x, w0.y, w0.z, w0.w, w1.x, w1.y, w1.z, w1.w};
        #pragma unroll
        for (int i = 0; i < 4; i++)
            #pragma unroll
            for (int j = 0; j < 8; j++)
                acc[i][j] = fmaf(av[i], wb[j], acc[i][j]);
    }
    __syncthreads();   // all phase-1 smem reads complete

    // bias + relu -> h written back into xs; stage W2
    {
        float bb[8];
        #pragma unroll
        for (int j = 0; j < 8; j++) bb[j] = b1[cbase + j];
        #pragma unroll
        for (int i = 0; i < 4; i++) {
            float4 h0, h1;
            h0.x = fmaxf(acc[i][0] + bb[0], 0.f);
            h0.y = fmaxf(acc[i][1] + bb[1], 0.f);
            h0.z = fmaxf(acc[i][2] + bb[2], 0.f);
            h0.w = fmaxf(acc[i][3] + bb[3], 0.f);
            h1.x = fmaxf(acc[i][4] + bb[4], 0.f);
            h1.y = fmaxf(acc[i][5] + bb[5], 0.f);
            h1.z = fmaxf(acc[i][6] + bb[6], 0.f);
            h1.w = fmaxf(acc[i][7] + bb[7], 0.f);
            float* rowp = xs + (4 * tr + i) * XS + cbase;
            reinterpret_cast<float4*>(rowp)[0] = h0;
            reinterpret_cast<float4*>(rowp)[1] = h1;
        }
    }
    for (int i = tid; i < DIM * DIM / 4; i += NTHREADS)
        reinterpret_cast<float4*>(ws)[i] = reinterpret_cast<const float4*>(W2)[i];
    __syncthreads();

    #pragma unroll
    for (int i = 0; i < 4; i++)
        #pragma unroll
        for (int j = 0; j < 8; j++) acc[i][j] = 0.f;

    #pragma unroll 4
    for (int k = 0; k < DIM; k++) {
        float av[4];
        #pragma unroll
        for (int i = 0; i < 4; i++) av[i] = xs[(4 * tr + i) * XS + k];
        float4 w0 = reinterpret_cast<const float4*>(ws + k * DIM)[2 * tc];
        float4 w1 = reinterpret_cast<const float4*>(ws + k * DIM)[2 * tc + 1];
        float wb[8] = {w0.x, w0.y, w0.z, w0.w, w1.x, w1.y, w1.z, w1.w};
        #pragma unroll
        for (int i = 0; i < 4; i++)
            #pragma unroll
            for (int j = 0; j < 8; j++)
                acc[i][j] = fmaf(av[i], wb[j], acc[i][j]);
    }

    {
        float bb[8];
        #pragma unroll
        for (int j = 0; j < 8; j++) bb[j] = b2[cbase + j];
        #pragma unroll
        for (int i = 0; i < 4; i++) {
            int r = row0 + 4 * tr + i;
            if (r < nrows) {
                float4 o0 = make_float4(acc[i][0] + bb[0], acc[i][1] + bb[1],
                                        acc[i][2] + bb[2], acc[i][3] + bb[3]);
                float4 o1 = make_float4(acc[i][4] + bb[4], acc[i][5] + bb[5],
                                        acc[i][6] + bb[6], acc[i][7] + bb[7]);
                float* rowp = out + (size_t)r * DIM + cbase;
                reinterpret_cast<float4*>(rowp)[0] = o0;
                reinterpret_cast<float4*>(rowp)[1] = o1;
            }
        }
    }
}

// ---------------------------------------------------------------------------
// Scatter-aggregate: AGG[rows[e]] += vals[e] * X[cols[e]]. One warp per edge.
__global__ void __launch_bounds__(NTHREADS)
scatter_kernel(const int* __restrict__ rows, const int* __restrict__ cols,
               const float* __restrict__ vals,
               const float* __restrict__ X, float* __restrict__ AGG, int E)
{
    int w = (int)((blockIdx.x * (unsigned)NTHREADS + threadIdx.x) >> 5);
    int lane = threadIdx.x & 31;
    if (w >= E) return;
    int r = __ldg(rows + w);
    int c = __ldg(cols + w);
    float v = __ldg(vals + w);
    float4 xv = reinterpret_cast<const float4*>(X + (size_t)c * DIM)[lane];
    float* dst = AGG + (size_t)r * DIM + 4 * lane;
    atomicAdd(dst + 0, v * xv.x);
    atomicAdd(dst + 1, v * xv.y);
    atomicAdd(dst + 2, v * xv.z);
    atomicAdd(dst + 3, v * xv.w);
}

// ---------------------------------------------------------------------------
// Fused gating: z,r,h gates + output. 6 GEMM passes over one smem W buffer.
__global__ void __launch_bounds__(NTHREADS, 1)
gate_kernel(const float* __restrict__ ob, const float* __restrict__ xb,
            const float* __restrict__ Wu1, const float* __restrict__ bu1,
            const float* __restrict__ Wu2, const float* __restrict__ bu2,
            const float* __restrict__ Wr1, const float* __restrict__ br1,
            const float* __restrict__ Wr2, const float* __restrict__ br2,
            const float* __restrict__ Wo1, const float* __restrict__ bo1,
            const float* __restrict__ Wo2, const float* __restrict__ bo2,
            float* __restrict__ y, int nrows)
{
    extern __shared__ float smem[];
    float* os = smem;                 // "out" tile
    float* xs = smem + TR * XS;       // "x" tile
    float* rs = smem + 2 * TR * XS;   // r*x tile
    float* ws = smem + 3 * TR * XS;   // weight buffer
    const int tid = threadIdx.x;
    const int tc = tid & 15;
    const int tr = tid >> 4;
    const int row0 = blockIdx.x * TR;
    const int cbase = 8 * tc;

    auto loadw = [&](const float* __restrict__ W) {
        for (int i = tid; i < DIM * DIM / 4; i += NTHREADS)
            reinterpret_cast<float4*>(ws)[i] = reinterpret_cast<const float4*>(W)[i];
    };
    auto mm = [&](const float* __restrict__ S, float (&acc)[4][8]) {
        #pragma unroll 4
        for (int k = 0; k < DIM; k++) {
            float av[4];
            #pragma unroll
            for (int i = 0; i < 4; i++) av[i] = S[(4 * tr + i) * XS + k];
            float4 w0 = reinterpret_cast<const float4*>(ws + k * DIM)[2 * tc];
            float4 w1 = reinterpret_cast<const float4*>(ws + k * DIM)[2 * tc + 1];
            float wb[8] = {w0.x, w0.y, w0.z, w0.w, w1.x, w1.y, w1.z, w1.w};
            #pragma unroll
            for (int i = 0; i < 4; i++)
                #pragma unroll
                for (int j = 0; j < 8; j++)
                    acc[i][j] = fmaf(av[i], wb[j], acc[i][j]);
        }
    };

    // load out/x tiles + Wu1
    for (int i = tid; i < TR * (DIM / 4); i += NTHREADS) {
        int r = i >> 5;
        int c4 = i & 31;
        float4 vo = make_float4(0.f, 0.f, 0.f, 0.f);
        float4 vx = make_float4(0.f, 0.f, 0.f, 0.f);
        if (row0 + r < nrows) {
            vo = reinterpret_cast<const float4*>(ob + (size_t)(row0 + r) * DIM)[c4];
            vx = reinterpret_cast<const float4*>(xb + (size_t)(row0 + r) * DIM)[c4];
        }
        reinterpret_cast<float4*>(os + r * XS)[c4] = vo;
        reinterpret_cast<float4*>(xs + r * XS)[c4] = vx;
    }
    loadw(Wu1);
    __syncthreads();

    float acc[4][8];
    float zg[4][8];

    // ---- z gate ----
    #pragma unroll
    for (int i = 0; i < 4; i++)
        #pragma unroll
        for (int j = 0; j < 8; j++) acc[i][j] = 0.f;
    mm(os, acc);
    __syncthreads();
    loadw(Wu2);
    __syncthreads();
    mm(xs, acc);
    {
        float bb[8];
        #pragma unroll
        for (int j = 0; j < 8; j++) bb[j] = bu1[cbase + j] + bu2[cbase + j];
        #pragma unroll
        for (int i = 0; i < 4; i++)
            #pragma unroll
            for (int j = 0; j < 8; j++) {
                float t = acc[i][j] + bb[j];
                zg[i][j] = 1.f / (1.f + expf(-t));
            }
    }
    __syncthreads();

    // ---- r gate -> rx tile ----
    loadw(Wr1);
    __syncthreads();
    #pragma unroll
    for (int i = 0; i < 4; i++)
        #pragma unroll
        for (int j = 0; j < 8; j++) acc[i][j] = 0.f;
    mm(os, acc);
    __syncthreads();
    loadw(Wr2);
    __syncthreads();
    mm(xs, acc);
    {
        float bb[8];
        #pragma unroll
        for (int j = 0; j < 8; j++) bb[j] = br1[cbase + j] + br2[cbase + j];
        #pragma unroll
        for (int i = 0; i < 4; i++) {
            float* rrow = rs + (4 * tr + i) * XS + cbase;
            const float* xrow = xs + (4 * tr + i) * XS + cbase;
            float4 r0, r1;
            float rv0 = 1.f / (1.f + expf(-(acc[i][0] + bb[0])));
            float rv1 = 1.f / (1.f + expf(-(acc[i][1] + bb[1])));
            float rv2 = 1.f / (1.f + expf(-(acc[i][2] + bb[2])));
            float rv3 = 1.f / (1.f + expf(-(acc[i][3] + bb[3])));
            float rv4 = 1.f / (1.f + expf(-(acc[i][4] + bb[4])));
            float rv5 = 1.f / (1.f + expf(-(acc[i][5] + bb[5])));
            float rv6 = 1.f / (1.f + expf(-(acc[i][6] + bb[6])));
            float rv7 = 1.f / (1.f + expf(-(acc[i][7] + bb[7])));
            r0 = make_float4(rv0 * xrow[0], rv1 * xrow[1], rv2 * xrow[2], rv3 * xrow[3]);
            r1 = make_float4(rv4 * xrow[4], rv5 * xrow[5], rv6 * xrow[6], rv7 * xrow[7]);
            reinterpret_cast<float4*>(rrow)[0] = r0;
            reinterpret_cast<float4*>(rrow)[1] = r1;
        }
    }
    __syncthreads();

    // ---- h gate ----
    loadw(Wo1);
    __syncthreads();
    #pragma unroll
    for (int i = 0; i < 4; i++)
        #pragma unroll
        for (int j = 0; j < 8; j++) acc[i][j] = 0.f;
    mm(os, acc);
    __syncthreads();
    loadw(Wo2);
    __syncthreads();
    mm(rs, acc);

    // ---- final output ----
    {
        float bb[8];
        #pragma unroll
        for (int j = 0; j < 8; j++) bb[j] = bo1[cbase + j] + bo2[cbase + j];
        #pragma unroll
        for (int i = 0; i < 4; i++) {
            int r = row0 + 4 * tr + i;
            if (r < nrows) {
                const float* xrow = xs + (4 * tr + i) * XS + cbase;
                float o[8];
                #pragma unroll
                for (int j = 0; j < 8; j++) {
                    float h = tanhf(acc[i][j] + bb[j]);
                    float z = zg[i][j];
                    o[j] = (1.f - z) * xrow[j] + z * h;
                }
                float* rowp = y + (size_t)r * DIM + cbase;
                reinterpret_cast<float4*>(rowp)[0] = make_float4(o[0], o[1], o[2], o[3]);
                reinterpret_cast<float4*>(rowp)[1] = make_float4(o[4], o[5], o[6], o[7]);
            }
        }
    }
}

// ---------------------------------------------------------------------------
extern "C" void kernel_launch(void* const* d_in, const int* in_sizes, int n_in,
                              void* d_out, int out_size)
{
    const float* x_in = (const float*)d_in[0];
    const int*   rows = (const int*)d_in[1];
    const int*   cols = (const int*)d_in[2];
    const float* vals = (const float*)d_in[3];
    const float* m1W1 = (const float*)d_in[4];
    const float* m1b1 = (const float*)d_in[5];
    const float* m1W2 = (const float*)d_in[6];
    const float* m1b2 = (const float*)d_in[7];
    const float* m2W1 = (const float*)d_in[8];
    const float* m2b1 = (const float*)d_in[9];
    const float* m2W2 = (const float*)d_in[10];
    const float* m2b2 = (const float*)d_in[11];
    const float* Wu1 = (const float*)d_in[12];
    const float* bu1 = (const float*)d_in[13];
    const float* Wu2 = (const float*)d_in[14];
    const float* bu2 = (const float*)d_in[15];
    const float* Wr1 = (const float*)d_in[16];
    const float* br1 = (const float*)d_in[17];
    const float* Wr2 = (const float*)d_in[18];
    const float* br2 = (const float*)d_in[19];
    const float* Wo1 = (const float*)d_in[20];
    const float* bo1 = (const float*)d_in[21];
    const float* Wo2 = (const float*)d_in[22];
    const float* bo2 = (const float*)d_in[23];

    int n = in_sizes[0] / DIM;
    int E = in_sizes[1];
    float* y = (float*)d_out;

    float *X, *AGG, *OUT;
    cudaGetSymbolAddress((void**)&X, g_X);
    cudaGetSymbolAddress((void**)&AGG, g_AGG);
    cudaGetSymbolAddress((void**)&OUT, g_OUT);

    cudaFuncSetAttribute(mlp2_kernel, cudaFuncAttributeMaxDynamicSharedMemorySize, SMEM_MLP);
    cudaFuncSetAttribute(gate_kernel, cudaFuncAttributeMaxDynamicSharedMemorySize, SMEM_GATE);

    int nb = (n + TR - 1) / TR;
    int n4 = n * DIM / 4;

    zero_kernel<<<(n4 + NTHREADS - 1) / NTHREADS, NTHREADS>>>((float4*)AGG, n4);
    mlp2_kernel<<<nb, NTHREADS, SMEM_MLP>>>(x_in, m1W1, m1b1, m1W2, m1b2, X, n);
    scatter_kernel<<<(E + 7) / 8, NTHREADS>>>(rows, cols, vals, X, AGG, E);
    mlp2_kernel<<<nb, NTHREADS, SMEM_MLP>>>(AGG, m2W1, m2b1, m2W2, m2b2, OUT, n);
    gate_kernel<<<nb, NTHREADS, SMEM_GATE>>>(OUT, X,
                                             Wu1, bu1, Wu2, bu2,
                                             Wr1, br1, Wr2, br2,
                                             Wo1, bo1, Wo2, bo2, y, n);
}

// round 4
// speedup vs baseline: 1.2672x; 1.2672x over previous
#include <cuda_runtime.h>
#include <math.h>
#include <stdint.h>

#define DIM 128
#define TR 64
#define XS 132            // padded smem row stride (floats); 528B keeps 16B align
#define NT 256
#define MAXN 50000

// scratch (allocation-free rule: device globals)
__device__ float g_X[(size_t)MAXN * DIM];
__device__ float g_AGG[(size_t)MAXN * DIM];
__device__ float g_OUT[(size_t)MAXN * DIM];

#define SMEM_MLP  ((TR * XS + DIM * DIM) * 4)
#define SMEM_GATE ((3 * TR * XS + DIM * DIM) * 4)

// ---------------- packed f32x2 helpers --------------------------------------
__device__ __forceinline__ void ffma2(uint64_t& acc, uint64_t a, uint64_t b) {
    asm("fma.rn.f32x2 %0, %1, %2, %0;" : "+l"(acc) : "l"(a), "l"(b));
}
__device__ __forceinline__ uint64_t dup2(float a) {
    uint64_t d;
    asm("mov.b64 %0, {%1, %1};" : "=l"(d) : "f"(a));
    return d;
}
__device__ __forceinline__ float2 unpk(uint64_t v) {
    float2 f;
    asm("mov.b64 {%0, %1}, %2;" : "=f"(f.x), "=f"(f.y) : "l"(v));
    return f;
}

// GEMM inner: 4 rows x 8 cols per thread, 16 FFMA2 per k.
// S: activation tile [TR][XS] row-major. ws: weights [128][128] k-major.
__device__ __forceinline__ void mm_f32x2(const float* __restrict__ S,
                                         const float* __restrict__ ws,
                                         int tr, int cbase, uint64_t (&acc)[4][4])
{
    #pragma unroll 8
    for (int k = 0; k < DIM; k++) {
        ulonglong2 w0 = *reinterpret_cast<const ulonglong2*>(ws + k * DIM + cbase);
        ulonglong2 w1 = *reinterpret_cast<const ulonglong2*>(ws + k * DIM + cbase + 4);
        #pragma unroll
        for (int i = 0; i < 4; i++) {
            uint64_t ad = dup2(S[(4 * tr + i) * XS + k]);
            ffma2(acc[i][0], ad, w0.x);
            ffma2(acc[i][1], ad, w0.y);
            ffma2(acc[i][2], ad, w1.x);
            ffma2(acc[i][3], ad, w1.y);
        }
    }
}
__device__ __forceinline__ void zero_acc(uint64_t (&acc)[4][4]) {
    #pragma unroll
    for (int i = 0; i < 4; i++)
        #pragma unroll
        for (int j = 0; j < 4; j++) acc[i][j] = 0ull;
}

// ---------------------------------------------------------------------------
// Fused 2-layer MLP: out = relu(in @ W1 + b1) @ W2 + b2
__global__ void __launch_bounds__(NT, 2)
mlp2_kernel(const float* __restrict__ in,
            const float* __restrict__ W1, const float* __restrict__ b1,
            const float* __restrict__ W2, const float* __restrict__ b2,
            float* __restrict__ out, int nrows)
{
    extern __shared__ float smem[];
    float* xs = smem;              // [TR][XS]
    float* ws = smem + TR * XS;    // [128][128]
    const int tid = threadIdx.x;
    const int tc = tid & 15;
    const int tr = tid >> 4;
    const int row0 = blockIdx.x * TR;
    const int cbase = 8 * tc;

    for (int i = tid; i < TR * (DIM / 4); i += NT) {
        int r = i >> 5, c4 = i & 31;
        float4 v = make_float4(0.f, 0.f, 0.f, 0.f);
        if (row0 + r < nrows)
            v = reinterpret_cast<const float4*>(in + (size_t)(row0 + r) * DIM)[c4];
        reinterpret_cast<float4*>(xs + r * XS)[c4] = v;
    }
    for (int i = tid; i < DIM * DIM / 4; i += NT)
        reinterpret_cast<float4*>(ws)[i] = reinterpret_cast<const float4*>(W1)[i];
    __syncthreads();

    uint64_t acc[4][4];
    zero_acc(acc);
    mm_f32x2(xs, ws, tr, cbase, acc);
    __syncthreads();

    // bias + relu -> back into xs; then stage W2
    {
        float bb[8];
        #pragma unroll
        for (int j = 0; j < 8; j++) bb[j] = b1[cbase + j];
        #pragma unroll
        for (int i = 0; i < 4; i++) {
            float2 p0 = unpk(acc[i][0]), p1 = unpk(acc[i][1]);
            float2 p2 = unpk(acc[i][2]), p3 = unpk(acc[i][3]);
            float4 h0 = make_float4(fmaxf(p0.x + bb[0], 0.f), fmaxf(p0.y + bb[1], 0.f),
                                    fmaxf(p1.x + bb[2], 0.f), fmaxf(p1.y + bb[3], 0.f));
            float4 h1 = make_float4(fmaxf(p2.x + bb[4], 0.f), fmaxf(p2.y + bb[5], 0.f),
                                    fmaxf(p3.x + bb[6], 0.f), fmaxf(p3.y + bb[7], 0.f));
            float* rowp = xs + (4 * tr + i) * XS + cbase;
            reinterpret_cast<float4*>(rowp)[0] = h0;
            reinterpret_cast<float4*>(rowp)[1] = h1;
        }
    }
    for (int i = tid; i < DIM * DIM / 4; i += NT)
        reinterpret_cast<float4*>(ws)[i] = reinterpret_cast<const float4*>(W2)[i];
    __syncthreads();

    zero_acc(acc);
    mm_f32x2(xs, ws, tr, cbase, acc);

    {
        float bb[8];
        #pragma unroll
        for (int j = 0; j < 8; j++) bb[j] = b2[cbase + j];
        #pragma unroll
        for (int i = 0; i < 4; i++) {
            int r = row0 + 4 * tr + i;
            if (r < nrows) {
                float2 p0 = unpk(acc[i][0]), p1 = unpk(acc[i][1]);
                float2 p2 = unpk(acc[i][2]), p3 = unpk(acc[i][3]);
                float4 o0 = make_float4(p0.x + bb[0], p0.y + bb[1], p1.x + bb[2], p1.y + bb[3]);
                float4 o1 = make_float4(p2.x + bb[4], p2.y + bb[5], p3.x + bb[6], p3.y + bb[7]);
                float* rowp = out + (size_t)r * DIM + cbase;
                reinterpret_cast<float4*>(rowp)[0] = o0;
                reinterpret_cast<float4*>(rowp)[1] = o1;
            }
        }
    }
}

// ---------------------------------------------------------------------------
// Scatter-aggregate: AGG[rows[e]] += vals[e] * X[cols[e]]. One warp per edge.
__global__ void __launch_bounds__(NT)
scatter_kernel(const int* __restrict__ rows, const int* __restrict__ cols,
               const float* __restrict__ vals,
               const float* __restrict__ X, float* __restrict__ AGG, int E)
{
    int w = blockIdx.x * (NT / 32) + (threadIdx.x >> 5);
    int lane = threadIdx.x & 31;
    if (w >= E) return;
    int r = __ldg(rows + w);
    int c = __ldg(cols + w);
    float v = __ldg(vals + w);
    float4 xv = reinterpret_cast<const float4*>(X + (size_t)c * DIM)[lane];
    float* dst = AGG + (size_t)r * DIM + 4 * lane;
    asm volatile("red.global.add.v4.f32 [%0], {%1, %2, %3, %4};"
                 :: "l"(dst), "f"(v * xv.x), "f"(v * xv.y), "f"(v * xv.z), "f"(v * xv.w)
                 : "memory");
}

// ---------------------------------------------------------------------------
// Fused gating: z,r,h gates + output. 6 GEMM passes over one smem W buffer.
__global__ void __launch_bounds__(NT, 1)
gate_kernel(const float* __restrict__ ob, const float* __restrict__ xb,
            const float* __restrict__ Wu1, const float* __restrict__ bu1,
            const float* __restrict__ Wu2, const float* __restrict__ bu2,
            const float* __restrict__ Wr1, const float* __restrict__ br1,
            const float* __restrict__ Wr2, const float* __restrict__ br2,
            const float* __restrict__ Wo1, const float* __restrict__ bo1,
            const float* __restrict__ Wo2, const float* __restrict__ bo2,
            float* __restrict__ y, int nrows)
{
    extern __shared__ float smem[];
    float* os = smem;                 // "out" tile / later r*x tile partner
    float* xs = smem + TR * XS;       // "x" tile
    float* rs = smem + 2 * TR * XS;   // r*x tile
    float* ws = smem + 3 * TR * XS;   // weight buffer
    const int tid = threadIdx.x;
    const int tc = tid & 15;
    const int tr = tid >> 4;
    const int row0 = blockIdx.x * TR;
    const int cbase = 8 * tc;

    auto loadw = [&](const float* __restrict__ W) {
        for (int i = tid; i < DIM * DIM / 4; i += NT)
            reinterpret_cast<float4*>(ws)[i] = reinterpret_cast<const float4*>(W)[i];
    };

    for (int i = tid; i < TR * (DIM / 4); i += NT) {
        int r = i >> 5, c4 = i & 31;
        float4 vo = make_float4(0.f, 0.f, 0.f, 0.f);
        float4 vx = make_float4(0.f, 0.f, 0.f, 0.f);
        if (row0 + r < nrows) {
            vo = reinterpret_cast<const float4*>(ob + (size_t)(row0 + r) * DIM)[c4];
            vx = reinterpret_cast<const float4*>(xb + (size_t)(row0 + r) * DIM)[c4];
        }
        reinterpret_cast<float4*>(os + r * XS)[c4] = vo;
        reinterpret_cast<float4*>(xs + r * XS)[c4] = vx;
    }
    loadw(Wu1);
    __syncthreads();

    uint64_t acc[4][4];
    float zg[4][8];

    // ---- z gate:  z = sigmoid(o@Wu1 + x@Wu2 + bu) ----
    zero_acc(acc);
    mm_f32x2(os, ws, tr, cbase, acc);
    __syncthreads();
    loadw(Wu2);
    __syncthreads();
    mm_f32x2(xs, ws, tr, cbase, acc);
    {
        float bb[8];
        #pragma unroll
        for (int j = 0; j < 8; j++) bb[j] = bu1[cbase + j] + bu2[cbase + j];
        #pragma unroll
        for (int i = 0; i < 4; i++) {
            float2 p[4] = {unpk(acc[i][0]), unpk(acc[i][1]), unpk(acc[i][2]), unpk(acc[i][3])};
            #pragma unroll
            for (int q = 0; q < 4; q++) {
                zg[i][2 * q]     = 1.f / (1.f + expf(-(p[q].x + bb[2 * q])));
                zg[i][2 * q + 1] = 1.f / (1.f + expf(-(p[q].y + bb[2 * q + 1])));
            }
        }
    }
    __syncthreads();

    // ---- r gate -> rs = r * x ----
    loadw(Wr1);
    __syncthreads();
    zero_acc(acc);
    mm_f32x2(os, ws, tr, cbase, acc);
    __syncthreads();
    loadw(Wr2);
    __syncthreads();
    mm_f32x2(xs, ws, tr, cbase, acc);
    {
        float bb[8];
        #pragma unroll
        for (int j = 0; j < 8; j++) bb[j] = br1[cbase + j] + br2[cbase + j];
        #pragma unroll
        for (int i = 0; i < 4; i++) {
            float2 p[4] = {unpk(acc[i][0]), unpk(acc[i][1]), unpk(acc[i][2]), unpk(acc[i][3])};
            const float* xrow = xs + (4 * tr + i) * XS + cbase;
            float rv[8];
            #pragma unroll
            for (int q = 0; q < 4; q++) {
                rv[2 * q]     = xrow[2 * q]     / (1.f + expf(-(p[q].x + bb[2 * q])));
                rv[2 * q + 1] = xrow[2 * q + 1] / (1.f + expf(-(p[q].y + bb[2 * q + 1])));
            }
            float* rrow = rs + (4 * tr + i) * XS + cbase;
            reinterpret_cast<float4*>(rrow)[0] = make_float4(rv[0], rv[1], rv[2], rv[3]);
            reinterpret_cast<float4*>(rrow)[1] = make_float4(rv[4], rv[5], rv[6], rv[7]);
        }
    }
    __syncthreads();

    // ---- h gate: h = tanh(o@Wo1 + (r*x)@Wo2 + bo) ----
    loadw(Wo1);
    __syncthreads();
    zero_acc(acc);
    mm_f32x2(os, ws, tr, cbase, acc);
    __syncthreads();
    loadw(Wo2);
    __syncthreads();
    mm_f32x2(rs, ws, tr, cbase, acc);

    // ---- final output ----
    {
        float bb[8];
        #pragma unroll
        for (int j = 0; j < 8; j++) bb[j] = bo1[cbase + j] + bo2[cbase + j];
        #pragma unroll
        for (int i = 0; i < 4; i++) {
            int r = row0 + 4 * tr + i;
            if (r < nrows) {
                float2 p[4] = {unpk(acc[i][0]), unpk(acc[i][1]), unpk(acc[i][2]), unpk(acc[i][3])};
                const float* xrow = xs + (4 * tr + i) * XS + cbase;
                float o[8];
                #pragma unroll
                for (int q = 0; q < 4; q++) {
                    float h0 = tanhf(p[q].x + bb[2 * q]);
                    float h1 = tanhf(p[q].y + bb[2 * q + 1]);
                    float z0 = zg[i][2 * q], z1 = zg[i][2 * q + 1];
                    o[2 * q]     = (1.f - z0) * xrow[2 * q]     + z0 * h0;
                    o[2 * q + 1] = (1.f - z1) * xrow[2 * q + 1] + z1 * h1;
                }
                float* rowp = y + (size_t)r * DIM + cbase;
                reinterpret_cast<float4*>(rowp)[0] = make_float4(o[0], o[1], o[2], o[3]);
                reinterpret_cast<float4*>(rowp)[1] = make_float4(o[4], o[5], o[6], o[7]);
            }
        }
    }
}

// ---------------------------------------------------------------------------
extern "C" void kernel_launch(void* const* d_in, const int* in_sizes, int n_in,
                              void* d_out, int out_size)
{
    const float* x_in = (const float*)d_in[0];
    const int*   rows = (const int*)d_in[1];
    const int*   cols = (const int*)d_in[2];
    const float* vals = (const float*)d_in[3];
    const float* m1W1 = (const float*)d_in[4];
    const float* m1b1 = (const float*)d_in[5];
    const float* m1W2 = (const float*)d_in[6];
    const float* m1b2 = (const float*)d_in[7];
    const float* m2W1 = (const float*)d_in[8];
    const float* m2b1 = (const float*)d_in[9];
    const float* m2W2 = (const float*)d_in[10];
    const float* m2b2 = (const float*)d_in[11];
    const float* Wu1 = (const float*)d_in[12];
    const float* bu1 = (const float*)d_in[13];
    const float* Wu2 = (const float*)d_in[14];
    const float* bu2 = (const float*)d_in[15];
    const float* Wr1 = (const float*)d_in[16];
    const float* br1 = (const float*)d_in[17];
    const float* Wr2 = (const float*)d_in[18];
    const float* br2 = (const float*)d_in[19];
    const float* Wo1 = (const float*)d_in[20];
    const float* bo1 = (const float*)d_in[21];
    const float* Wo2 = (const float*)d_in[22];
    const float* bo2 = (const float*)d_in[23];

    int n = in_sizes[0] / DIM;
    int E = in_sizes[1];
    float* y = (float*)d_out;

    float *X, *AGG, *OUT;
    cudaGetSymbolAddress((void**)&X, g_X);
    cudaGetSymbolAddress((void**)&AGG, g_AGG);
    cudaGetSymbolAddress((void**)&OUT, g_OUT);

    cudaFuncSetAttribute(mlp2_kernel, cudaFuncAttributeMaxDynamicSharedMemorySize, SMEM_MLP);
    cudaFuncSetAttribute(gate_kernel, cudaFuncAttributeMaxDynamicSharedMemorySize, SMEM_GATE);

    int nb = (n + TR - 1) / TR;

    cudaMemsetAsync(AGG, 0, (size_t)n * DIM * sizeof(float));
    mlp2_kernel<<<nb, NT, SMEM_MLP>>>(x_in, m1W1, m1b1, m1W2, m1b2, X, n);
    scatter_kernel<<<(E + 7) / 8, NT>>>(rows, cols, vals, X, AGG, E);
    mlp2_kernel<<<nb, NT, SMEM_MLP>>>(AGG, m2W1, m2b1, m2W2, m2b2, OUT, n);
    gate_kernel<<<nb, NT, SMEM_GATE>>>(OUT, X,
                                       Wu1, bu1, Wu2, bu2,
                                       Wr1, br1, Wr2, br2,
                                       Wo1, bo1, Wo2, bo2, y, n);
}